// round 16
// baseline (speedup 1.0000x reference)
#include <cuda_runtime.h>
#include <cstdint>
#include <math.h>

#define BATCH 8
#define CIN   28
#define COUT  28
#define HH    256
#define WW    256
#define DGRP  7
#define KHT   7
#define CPG   4
#define HW    (HH*WW)

typedef unsigned long long ull;

__device__ __forceinline__ ull pk2(float a, float b) {
    ull r; asm("mov.b64 %0, {%1,%2};" : "=l"(r) : "f"(a), "f"(b)); return r;
}
__device__ __forceinline__ ull pk1(float a) { return pk2(a, a); }
__device__ __forceinline__ ull f2fma(ull a, ull b, ull c) {
    ull d; asm("fma.rn.f32x2 %0, %1, %2, %3;" : "=l"(d) : "l"(a), "l"(b), "l"(c)); return d;
}
__device__ __forceinline__ ull f2mul(ull a, ull b) {
    ull d; asm("mul.rn.f32x2 %0, %1, %2;" : "=l"(d) : "l"(a), "l"(b)); return d;
}
__device__ __forceinline__ void cp16(void* dst, const void* src) {
    unsigned s = (unsigned)__cvta_generic_to_shared(dst);
    asm volatile("cp.async.cg.shared.global [%0], [%1], 16;" :: "r"(s), "l"(src));
}
__device__ __forceinline__ ull splat_dev(float v) {
    unsigned u = __float_as_uint(v); return ((ull)u << 32) | (ull)u;
}

// ---- global scratch ----
__device__ float g_mid[(size_t)BATCH * COUT * HH * WW];   // 58.7MB stage-1 output
__device__ ull   g_W1P[2 * DGRP * KHT * CPG * 2 * 7];     // [tap][c][ohh][j] -> ull2 pair
__device__ ull   g_W2P[2 * COUT * 7 * 4 * 4];             // [o2][kw][ohq][j] -> ull2 pair (ch pad)
__device__ float g_b2[COUT];

__global__ void prep_kernel(const float* __restrict__ weight, const float* __restrict__ w_t,
                            const float* __restrict__ b_t, const float* __restrict__ w_m,
                            const float* __restrict__ b_m) {
    int gid = blockIdx.x * blockDim.x + threadIdx.x;
    int nth = gridDim.x * blockDim.x;

    for (int e = gid; e < 2744; e += nth) {
        int j = e % 7; int r = e / 7;
        int ohh = r & 1; r >>= 1;
        int c = r & 3; int tap = r >> 2;
        int g = tap / 7, i = tap % 7;
        int o0 = ohh * 14 + 2 * j;
        float wa = weight[(o0 * CIN + (g * CPG + c)) * KHT + i];
        float wb = weight[((o0 + 1) * CIN + (g * CPG + c)) * KHT + i];
        g_W1P[2 * e]     = splat_dev(wa);
        g_W1P[2 * e + 1] = splat_dev(wb);
    }

    for (int e2 = gid; e2 < 3136; e2 += nth) {
        int j = e2 & 3; int q = e2 >> 2;
        int ohq = q & 3; q >>= 2;
        int kw = q % 7; int o2 = q / 7;
        float va = 0.f, vb = 0.f;
        int oc0 = ohq * 7 + 2 * j;
        {
            int f = oc0 >> 2, cc = oc0 & 3;
#pragma unroll
            for (int g = 0; g < DGRP; g++)
                va += w_m[f * DGRP + g] * w_t[((g * CPG + cc) * COUT + o2) * 7 + kw];
        }
        if (2 * j + 1 < 7) {
            int oc1 = oc0 + 1;
            int f = oc1 >> 2, cc = oc1 & 3;
#pragma unroll
            for (int g = 0; g < DGRP; g++)
                vb += w_m[f * DGRP + g] * w_t[((g * CPG + cc) * COUT + o2) * 7 + kw];
        }
        g_W2P[2 * e2]     = splat_dev(va);
        g_W2P[2 * e2 + 1] = splat_dev(vb);
    }

    if (gid < COUT) {
        int f = gid >> 2, cc = gid & 3;
        float s = 0.f;
#pragma unroll
        for (int g = 0; g < DGRP; g++) s += w_m[f * DGRP + g] * b_t[g * CPG + cc];
        g_b2[gid] = s + b_m[f];
    }
}

// ============ Stage 1: 2 h-rows per THREAD, weight LDS amortized ============
// 256 threads: p = tid&127 -> w-pair (2p, 2p+1); ohh = tid>>7 -> 14-channel half.
// Each thread accumulates both h-rows; W1 weights loaded once per tap.
constexpr int A_W1   = 0;                        // ull[5488] 43904
constexpr int A_B1   = 43904;                    // float[32] 128
constexpr int A_TL0  = 44032;                    // ull[128]  (hz*64+t)
constexpr int A_TL1  = A_TL0 + 1024;             // ull[128]
constexpr int A_TY0  = A_TL1 + 1024;             // int[128] (premult WW)
constexpr int A_TY1  = A_TY0 + 512;              // int[128]
constexpr int A_MT   = A_TY1 + 512;              // int[64] tap
constexpr int A_MG   = A_MT + 256;               // int[64] g
constexpr int A_MY00 = A_MG + 256;               // int[64] h0 y0
constexpr int A_MY01 = A_MY00 + 256;             // int[64] h0 y1
constexpr int A_MY10 = A_MY01 + 256;             // int[64] h1 y0
constexpr int A_MY11 = A_MY10 + 256;             // int[64] h1 y1
constexpr int A_ML00 = A_MY11 + 256;             // ull[64] h0 lerp0
constexpr int A_ML01 = A_ML00 + 512;
constexpr int A_ML10 = A_ML01 + 512;
constexpr int A_ML11 = A_ML10 + 512;
constexpr int A_NL   = A_ML11 + 512;             // int
constexpr int A_SMEM = A_NL + 16;                // ~49.6KB -> 2 CTAs/SM

__global__ void __launch_bounds__(256, 2)
stage1_kernel(const float* __restrict__ x, const float* __restrict__ bias1) {
    extern __shared__ char sm[];
    ull*   W1p  = (ull*)(sm + A_W1);
    float* b1s  = (float*)(sm + A_B1);
    ull*   tl0  = (ull*)(sm + A_TL0);
    ull*   tl1  = (ull*)(sm + A_TL1);
    int*   ty0  = (int*)(sm + A_TY0);
    int*   ty1  = (int*)(sm + A_TY1);
    int*   mTap = (int*)(sm + A_MT);
    int*   mG   = (int*)(sm + A_MG);
    int*   mY00 = (int*)(sm + A_MY00);
    int*   mY01 = (int*)(sm + A_MY01);
    int*   mY10 = (int*)(sm + A_MY10);
    int*   mY11 = (int*)(sm + A_MY11);
    ull*   mL00 = (ull*)(sm + A_ML00);
    ull*   mL01 = (ull*)(sm + A_ML01);
    ull*   mL10 = (ull*)(sm + A_ML10);
    ull*   mL11 = (ull*)(sm + A_ML11);
    int*   nLp  = (int*)(sm + A_NL);

    const int tid = threadIdx.x;
    const int h0 = blockIdx.x * 2;
    const int b  = blockIdx.y;

    for (int i = tid; i < 5488; i += 256) W1p[i] = g_W1P[i];
    if (tid < 28) b1s[tid] = bias1[tid];

    if (tid < 49) {
#pragma unroll
        for (int hz = 0; hz < 2; hz++) {
            int g = tid / 7, i = tid % 7;
            int h = h0 + hz;
            double yp = (double)((h + 1) * (i + 1)) / (double)(g + 1) - 4.0;
            double y0 = floor(yp);
            float fy = (float)(yp - y0);
            int y0i = (int)y0;
            bool v0 = (y0i >= 0) && (y0i <= HH - 1);
            bool v1 = (y0i + 1 >= 0) && (y0i + 1 <= HH - 1);
            int ya = y0i < 0 ? 0 : (y0i > HH - 1 ? HH - 1 : y0i);
            int yb = (y0i + 1) < 0 ? 0 : (y0i + 1 > HH - 1 ? HH - 1 : y0i + 1);
            ty0[hz * 64 + tid] = ya * WW;
            ty1[hz * 64 + tid] = yb * WW;
            tl0[hz * 64 + tid] = v0 ? pk1(1.0f - fy) : 0ull;
            tl1[hz * 64 + tid] = v1 ? pk1(fy) : 0ull;
        }
    }
    __syncthreads();
    if (tid == 0) {
        int n = 0;
        for (int k = 0; k < 49; k++) {
            ull live = tl0[k] | tl1[k] | tl0[64 + k] | tl1[64 + k];
            if (live != 0ull) {
                mTap[n] = k; mG[n] = k / 7;
                mY00[n] = ty0[k];      mY01[n] = ty1[k];
                mY10[n] = ty0[64 + k]; mY11[n] = ty1[64 + k];
                mL00[n] = tl0[k];      mL01[n] = tl1[k];
                mL10[n] = tl0[64 + k]; mL11[n] = tl1[64 + k];
                n++;
            }
        }
        *nLp = n;
    }
    __syncthreads();

    const int p = tid & 127;
    const int ohh = tid >> 7;
    const int wbase = 2 * p;

    ull acc[2][14];
#pragma unroll
    for (int o = 0; o < 14; o++) {
        ull bv = pk1(b1s[ohh * 14 + o]);
        acc[0][o] = bv; acc[1][o] = bv;
    }

    const float* xb = x + (size_t)b * CIN * HW + wbase;
    const int nl = *nLp;

#pragma unroll 1
    for (int tt = 0; tt < nl; tt++) {
        const int tap = mTap[tt];
        const int g   = mG[tt];
        const int y00 = mY00[tt], y01 = mY01[tt];
        const int y10 = mY10[tt], y11 = mY11[tt];
        const ull l00 = mL00[tt], l01 = mL01[tt];
        const ull l10 = mL10[tt], l11 = mL11[tt];
        const float* rb = xb + (size_t)g * CPG * HW;

        ull s0[4], s1[4];
#pragma unroll
        for (int c = 0; c < 4; c++) {
            const float* cr = rb + (size_t)c * HW;
            ull a0 = *(const ull*)(cr + y00);
            ull a1 = *(const ull*)(cr + y01);
            ull b0v = *(const ull*)(cr + y10);
            ull b1v = *(const ull*)(cr + y11);
            s0[c] = f2fma(l01, a1, f2mul(l00, a0));
            s1[c] = f2fma(l11, b1v, f2mul(l10, b0v));
        }
#pragma unroll
        for (int c = 0; c < 4; c++) {
            const ulonglong2* wc = (const ulonglong2*)W1p + ((tap * 4 + c) * 2 + ohh) * 7;
#pragma unroll
            for (int j = 0; j < 7; j++) {
                ulonglong2 w = wc[j];
                acc[0][2 * j]     = f2fma(w.x, s0[c], acc[0][2 * j]);
                acc[1][2 * j]     = f2fma(w.x, s1[c], acc[1][2 * j]);
                acc[0][2 * j + 1] = f2fma(w.y, s0[c], acc[0][2 * j + 1]);
                acc[1][2 * j + 1] = f2fma(w.y, s1[c], acc[1][2 * j + 1]);
            }
        }
    }

#pragma unroll
    for (int hz = 0; hz < 2; hz++) {
        float* mb = g_mid + (((size_t)b * COUT + ohh * 14) * HH + (h0 + hz)) * WW + wbase;
#pragma unroll
        for (int o = 0; o < 14; o++)
            *(ull*)(mb + (size_t)o * HW) = acc[hz][o];
    }
}

// ============== Stage 2 (+3 folded): 2 h-rows per CTA (R12, unchanged) =======
constexpr int B_W2   = 0;                        // ull[6272] 50176
constexpr int B_B2   = 50176;                    // float[32] 128
constexpr int B_R    = 50304;                    // float[2*28*264] 59136
constexpr int B_ROWS = 7392;                     // floats per h-row block (28*264)
constexpr int B_SMEM = B_R + 59136;              // 109440 (~106.9KB) -> 2 CTAs/SM

__global__ void __launch_bounds__(256, 2)
stage2_kernel(float* __restrict__ out) {
    extern __shared__ char sm[];
    ull*   W2p = (ull*)(sm + B_W2);
    float* b2s = (float*)(sm + B_B2);
    float* R   = (float*)(sm + B_R);

    const int tid = threadIdx.x;
    const int h0 = blockIdx.x * 2;
    const int b = blockIdx.y;

#pragma unroll
    for (int hz = 0; hz < 2; hz++) {
        const float* mrow = g_mid + ((size_t)b * COUT * HH + (h0 + hz)) * WW;
#pragma unroll
        for (int k = 0; k < 7; k++) {
            int idx = tid + 256 * k;
            int row = idx >> 6;
            int ch  = idx & 63;
            cp16(R + hz * B_ROWS + row * 264 + 4 + ch * 4, mrow + (size_t)row * HW + ch * 4);
        }
    }
    asm volatile("cp.async.commit_group;" ::: "memory");

    for (int i = tid; i < 6272; i += 256) W2p[i] = g_W2P[i];
    if (tid < 28) b2s[tid] = g_b2[tid];
    if (tid < 56) {
        int hz = tid / 28, row = tid % 28;
        float* Rr = R + hz * B_ROWS + row * 264;
        Rr[0] = Rr[1] = Rr[2] = Rr[3] = 0.f;
        Rr[260] = Rr[261] = Rr[262] = Rr[263] = 0.f;
    }
    asm volatile("cp.async.wait_group 0;" ::: "memory");
    __syncthreads();

    const int p = tid & 63;
    const int ohq = tid >> 6;
    const int base = 4 * p;

    ull acc[2][7][2];
#pragma unroll
    for (int o = 0; o < 7; o++) {
        ull bv = pk1(b2s[ohq * 7 + o]);
        acc[0][o][0] = bv; acc[0][o][1] = bv;
        acc[1][o][0] = bv; acc[1][o][1] = bv;
    }

#pragma unroll 1
    for (int o2 = 0; o2 < 28; o2++) {
        float r0[12], r1[12];
        {
            const float4* Rw0 = (const float4*)(R + o2 * 264 + base);
            *(float4*)(r0)     = Rw0[0];
            *(float4*)(r0 + 4) = Rw0[1];
            *(float4*)(r0 + 8) = Rw0[2];
            const float4* Rw1 = (const float4*)(R + B_ROWS + o2 * 264 + base);
            *(float4*)(r1)     = Rw1[0];
            *(float4*)(r1 + 4) = Rw1[1];
            *(float4*)(r1 + 8) = Rw1[2];
        }
#pragma unroll
        for (int kw = 0; kw < 7; kw++) {
            const ulonglong2* wq = (const ulonglong2*)W2p + (((o2 * 7 + kw) * 4 + ohq) << 2);
            ulonglong2 w0 = wq[0], w1 = wq[1], w2 = wq[2], w3 = wq[3];
            {
                ull vA = pk2(r0[kw + 1], r0[kw + 2]);
                ull vB = pk2(r0[kw + 3], r0[kw + 4]);
                acc[0][0][0] = f2fma(w0.x, vA, acc[0][0][0]); acc[0][0][1] = f2fma(w0.x, vB, acc[0][0][1]);
                acc[0][1][0] = f2fma(w0.y, vA, acc[0][1][0]); acc[0][1][1] = f2fma(w0.y, vB, acc[0][1][1]);
                acc[0][2][0] = f2fma(w1.x, vA, acc[0][2][0]); acc[0][2][1] = f2fma(w1.x, vB, acc[0][2][1]);
                acc[0][3][0] = f2fma(w1.y, vA, acc[0][3][0]); acc[0][3][1] = f2fma(w1.y, vB, acc[0][3][1]);
                acc[0][4][0] = f2fma(w2.x, vA, acc[0][4][0]); acc[0][4][1] = f2fma(w2.x, vB, acc[0][4][1]);
                acc[0][5][0] = f2fma(w2.y, vA, acc[0][5][0]); acc[0][5][1] = f2fma(w2.y, vB, acc[0][5][1]);
                acc[0][6][0] = f2fma(w3.x, vA, acc[0][6][0]); acc[0][6][1] = f2fma(w3.x, vB, acc[0][6][1]);
            }
            {
                ull vA = pk2(r1[kw + 1], r1[kw + 2]);
                ull vB = pk2(r1[kw + 3], r1[kw + 4]);
                acc[1][0][0] = f2fma(w0.x, vA, acc[1][0][0]); acc[1][0][1] = f2fma(w0.x, vB, acc[1][0][1]);
                acc[1][1][0] = f2fma(w0.y, vA, acc[1][1][0]); acc[1][1][1] = f2fma(w0.y, vB, acc[1][1][1]);
                acc[1][2][0] = f2fma(w1.x, vA, acc[1][2][0]); acc[1][2][1] = f2fma(w1.x, vB, acc[1][2][1]);
                acc[1][3][0] = f2fma(w1.y, vA, acc[1][3][0]); acc[1][3][1] = f2fma(w1.y, vB, acc[1][3][1]);
                acc[1][4][0] = f2fma(w2.x, vA, acc[1][4][0]); acc[1][4][1] = f2fma(w2.x, vB, acc[1][4][1]);
                acc[1][5][0] = f2fma(w2.y, vA, acc[1][5][0]); acc[1][5][1] = f2fma(w2.y, vB, acc[1][5][1]);
                acc[1][6][0] = f2fma(w3.x, vA, acc[1][6][0]); acc[1][6][1] = f2fma(w3.x, vB, acc[1][6][1]);
            }
        }
    }

#pragma unroll
    for (int hz = 0; hz < 2; hz++) {
        float* ob = out + (((size_t)b * COUT + ohq * 7) * HH + (h0 + hz)) * WW + base;
#pragma unroll
        for (int o = 0; o < 7; o++) {
            ulonglong2 v; v.x = acc[hz][o][0]; v.y = acc[hz][o][1];
            *(ulonglong2*)(ob + (size_t)o * HW) = v;
        }
    }
}

extern "C" void kernel_launch(void* const* d_in, const int* in_sizes, int n_in,
                              void* d_out, int out_size) {
    const float* x      = (const float*)d_in[0];
    const float* weight = (const float*)d_in[1];
    const float* bias   = (const float*)d_in[2];
    const float* w_t    = (const float*)d_in[3];
    const float* b_t    = (const float*)d_in[4];
    const float* w_m    = (const float*)d_in[5];
    const float* b_m    = (const float*)d_in[6];
    float* out = (float*)d_out;

    cudaFuncSetAttribute(stage1_kernel, cudaFuncAttributeMaxDynamicSharedMemorySize, A_SMEM);
    cudaFuncSetAttribute(stage2_kernel, cudaFuncAttributeMaxDynamicSharedMemorySize, B_SMEM);

    prep_kernel<<<32, 256>>>(weight, w_t, b_t, w_m, b_m);
    stage1_kernel<<<dim3(HH / 2, BATCH), 256, A_SMEM>>>(x, bias);
    stage2_kernel<<<dim3(HH / 2, BATCH), 256, B_SMEM>>>(out);
}